// round 1
// baseline (speedup 1.0000x reference)
#include <cuda_runtime.h>
#include <cuda_bf16.h>
#include <math.h>

// Problem constants (fixed shapes from the reference)
constexpr int B_   = 16;
constexpr int T_   = 64;
constexpr int HWC  = 32 * 32 * 64;   // 65536 elements per (b, t) slab
constexpr int PV   = HWC / 4;        // float4 vectors per slab = 16384
constexpr int NVEC = B_ * PV;        // total vec-threads = 262144

__global__ __launch_bounds__(256)
void alif2d_kernel(const float4* __restrict__ x,        // [B, T, HWC/4]
                   const float*  __restrict__ hp_base_step,
                   const float*  __restrict__ hp_base_decay,
                   const float4* __restrict__ step_w_raw, // [HWC/4]
                   const float4* __restrict__ decay_w_raw,
                   const float4* __restrict__ gamma,
                   const float4* __restrict__ beta,
                   float4* __restrict__ out_s,            // [B, T, HWC/4]
                   float4* __restrict__ out_v)            // [B, T, HWC/4]
{
    const int idx = blockIdx.x * blockDim.x + threadIdx.x;
    if (idx >= NVEC) return;

    const int p = idx & (PV - 1);     // position within HWC slab (vec units)
    const int b = idx >> 14;          // idx / PV  (PV = 16384 = 2^14)

    const float bs = *hp_base_step;
    const float bd = *hp_base_decay;

    const float4 swr = step_w_raw[p];
    const float4 dwr = decay_w_raw[p];
    const float4 g4  = gamma[p];
    const float4 be4 = beta[p];

    float g[4]   = {g4.x, g4.y, g4.z, g4.w};
    float be[4]  = {be4.x, be4.y, be4.z, be4.w};
    float swra[4]= {swr.x, swr.y, swr.z, swr.w};
    float dwra[4]= {dwr.x, dwr.y, dwr.z, dwr.w};

    float step_eff[4], decay_eff[4];
#pragma unroll
    for (int i = 0; i < 4; i++) {
        // softplus(x) = log1p(exp(x)); sigmoid(x) = 1/(1+exp(-x))
        float sp  = log1pf(expf(swra[i]));
        float sig = 1.0f / (1.0f + expf(-dwra[i]));
        step_eff[i]  = bs * sp;
        decay_eff[i] = bd + (1.0f - bd) * sig;
    }

    float v[4]   = {0.f, 0.f, 0.f, 0.f};
    float vth[4] = {0.f, 0.f, 0.f, 0.f};

    const float4* xp = x     + (size_t)b * T_ * PV + p;
    float4*       sp = out_s + (size_t)b * T_ * PV + p;
    float4*       vp = out_v + (size_t)b * T_ * PV + p;

#pragma unroll 4
    for (int t = 0; t < T_; t++) {
        const float4 xv = __ldg(xp + (size_t)t * PV);
        float xa[4] = {xv.x, xv.y, xv.z, xv.w};

        float s_out[4], v_out[4];
#pragma unroll
        for (int i = 0; i < 4; i++) {
            // v = v*0.8 + (x*gamma + beta)
            float vi = fmaf(v[i], 0.8f, fmaf(xa[i], g[i], be[i]));
            float vth_eff = 0.5f + vth[i];
            float s = (vi - vth_eff > 0.0f) ? 1.0f : 0.0f;
            v_out[i] = vi;            // voltages output is pre-reset v
            s_out[i] = s;
            v[i]   = vi - vth_eff * s;
            vth[i] = fmaf(vth[i], decay_eff[i], s * step_eff[i]);
        }

        float4 s4 = make_float4(s_out[0], s_out[1], s_out[2], s_out[3]);
        float4 v4 = make_float4(v_out[0], v_out[1], v_out[2], v_out[3]);
        sp[(size_t)t * PV] = s4;
        vp[(size_t)t * PV] = v4;
    }
}

extern "C" void kernel_launch(void* const* d_in, const int* in_sizes, int n_in,
                              void* d_out, int out_size)
{
    // metadata order: x, hp_alpha, hp_base_step, hp_base_decay,
    //                 step_w_raw, decay_w_raw, gamma, beta
    const float4* x    = (const float4*)d_in[0];
    // d_in[1] = hp_alpha (unused in forward pass)
    const float*  hbs  = (const float*)d_in[2];
    const float*  hbd  = (const float*)d_in[3];
    const float4* swr  = (const float4*)d_in[4];
    const float4* dwr  = (const float4*)d_in[5];
    const float4* gam  = (const float4*)d_in[6];
    const float4* bet  = (const float4*)d_in[7];

    const size_t n_per = (size_t)B_ * T_ * HWC;   // 67,108,864 elements
    float4* out_s = (float4*)d_out;
    float4* out_v = (float4*)((float*)d_out + n_per);

    const int threads = 256;
    const int blocks  = (NVEC + threads - 1) / threads;  // 1024
    alif2d_kernel<<<blocks, threads>>>(x, hbs, hbd, swr, dwr, gam, bet,
                                       out_s, out_v);
}